// round 16
// baseline (speedup 1.0000x reference)
#include <cuda_runtime.h>
#include <cuda_fp16.h>
#include <cstdint>
#include <math.h>

// Problem constants
#define BATCH 4
#define SEQ   2048
#define DQ    1024
#define DKV   768
#define NH    4
#define HD    256

// HMMA GEMM tiling: 128x128 CTA tile, K-tile 64, double-buffered cp.async
#define TBM 128
#define TBN 128
#define TBK 64
#define NTHREADS 256
#define ROWB  144                      // 64 halfs (128B) + 16B pad
#define ATILE (128 * ROWB)             // 18432
#define STAGEB (2 * ATILE)             // 36864
#define NSTAGE 2
#define SMEM_TOTAL (NSTAGE * STAGEB)   // 73728 B  (2 CTAs/SM)

// NN-mode B tile: 64 k-rows x 128 n-cols fp16, 16B row pad
#define BROWB 272
#define BTILE (64 * BROWB)             // 17408
#define STAGEB_NN (ATILE + BTILE)      // 35840
#define SMEM_NN (NSTAGE * STAGEB_NN)   // 71680 B

#define QK_SCALE 0.09016844005555897f  // log2(e) / 16

// -------- scratch (device globals; no cudaMalloc allowed) -------------------
__device__ __half g_q16 [(long long)BATCH * SEQ * DQ];
__device__ __half g_kv16[(long long)BATCH * SEQ * DKV];
__device__ __half g_wq16[DQ * DQ];
__device__ __half g_wkv16[2 * DQ * DKV];                       // [Wk;Wv] rows
__device__ __half g_wo16[DQ * DQ];
__device__ __half g_qp16 [(long long)BATCH * SEQ * DQ];
__device__ __half g_kvp16[(long long)BATCH * SEQ * 2 * DQ];    // kp | vp cols
__device__ __half g_ctx16[(long long)BATCH * SEQ * DQ];
__device__ __half g_sc16 [(long long)BATCH * NH * SEQ * SEQ];  // fp16 scores
__device__ __half g_p16  [(long long)BATCH * NH * SEQ * SEQ];  // fp16 probs

// ---------------------------- helpers ---------------------------------------
__device__ __forceinline__ uint32_t smem_u32(const void* p) {
    uint32_t a;
    asm("{ .reg .u64 t; cvta.to.shared.u64 t, %1; cvt.u32.u64 %0, t; }"
        : "=r"(a) : "l"(p));
    return a;
}

__device__ __forceinline__ void cp16(uint32_t dst, const void* src) {
    asm volatile("cp.async.cg.shared.global [%0], [%1], 16;"
                 :: "r"(dst), "l"(src) : "memory");
}

__device__ __forceinline__ void ldsm4(uint32_t addr, uint32_t& r0, uint32_t& r1,
                                      uint32_t& r2, uint32_t& r3) {
    asm volatile("ldmatrix.sync.aligned.m8n8.x4.shared.b16 {%0,%1,%2,%3}, [%4];"
                 : "=r"(r0), "=r"(r1), "=r"(r2), "=r"(r3) : "r"(addr));
}

__device__ __forceinline__ void ldsm4t(uint32_t addr, uint32_t& r0, uint32_t& r1,
                                       uint32_t& r2, uint32_t& r3) {
    asm volatile("ldmatrix.sync.aligned.m8n8.x4.trans.shared.b16 {%0,%1,%2,%3}, [%4];"
                 : "=r"(r0), "=r"(r1), "=r"(r2), "=r"(r3) : "r"(addr));
}

__device__ __forceinline__ void mma16816(float* c, const uint32_t* a,
                                         const uint32_t* b) {
    asm volatile(
        "mma.sync.aligned.m16n8k16.row.col.f32.f16.f16.f32 "
        "{%0,%1,%2,%3}, {%4,%5,%6,%7}, {%8,%9}, {%0,%1,%2,%3};"
        : "+f"(c[0]), "+f"(c[1]), "+f"(c[2]), "+f"(c[3])
        : "r"(a[0]), "r"(a[1]), "r"(a[2]), "r"(a[3]), "r"(b[0]), "r"(b[1]));
}

__device__ __forceinline__ float exp2a(float x) {
    float r;
    asm("ex2.approx.f32 %0, %1;" : "=f"(r) : "f"(x));
    return r;
}

// ---------------------------------------------------------------------------
// Segmented fp32 -> fp16 conversion: 6 segments passed BY VALUE (capture-safe)
// ---------------------------------------------------------------------------
struct ConvSeg { const float4* s; uint2* d; long long n; float m; };
struct ConvArgs { ConvSeg seg[6]; };

__global__ void conv6_kernel(ConvArgs a, long long total)
{
    long long i = (long long)blockIdx.x * blockDim.x + threadIdx.x;
    if (i >= total) return;
    #pragma unroll
    for (int k = 0; k < 6; ++k) {
        if (i < a.seg[k].n) {
            float4 v = a.seg[k].s[i];
            const float m = a.seg[k].m;
            __half2 h0 = __floats2half2_rn(v.x * m, v.y * m);
            __half2 h1 = __floats2half2_rn(v.z * m, v.w * m);
            uint2 u;
            u.x = *reinterpret_cast<uint32_t*>(&h0);
            u.y = *reinterpret_cast<uint32_t*>(&h1);
            a.seg[k].d[i] = u;
            return;
        }
        i -= a.seg[k].n;
    }
}

// ---------------------------------------------------------------------------
// HMMA fp16 NT GEMM, TBK=64, double-buffered cp.async, 2 CTAs/SM.
//   C[m,n] = alpha * sum_k A[m,k]*B[n,k]  (+ bias[n] if mode 0)
// outMode: 0 = fp32 C (+bias), 1 = fp16 C.  K % 64 == 0.
// ---------------------------------------------------------------------------
__global__ __launch_bounds__(NTHREADS, 2)
void gemm_hmma16(const __half* __restrict__ A, const __half* __restrict__ B,
                 const float* __restrict__ bias, void* __restrict__ Cv,
                 int K, int lda, int ldb, int ldc, int nh,
                 long long sAb, long long sAh, long long sBb, long long sBh,
                 long long sCb, long long sCh, float alpha, int outMode)
{
    extern __shared__ __align__(16) char sm[];
    const uint32_t smbase = smem_u32(sm);

    const int tid = threadIdx.x;
    const int lane = tid & 31, wid = tid >> 5;
    const int wm = wid & 3, wn = wid >> 2;

    const int z = blockIdx.z, bz = z / nh, hz = z - bz * nh;
    A += bz * sAb + hz * sAh;
    B += bz * sBb + hz * sBh;
    const int bm = blockIdx.y * TBM, bn = blockIdx.x * TBN;

    // staging: 2 threads/row, 4x16B chunks each
    const int srow = tid >> 1;
    const int sh   = tid & 1;
    const __half* gA = A + (long long)(bm + srow) * lda + sh * 32;
    const __half* gB = B + (long long)(bn + srow) * ldb + sh * 32;
    const uint32_t stsA = smbase + (uint32_t)srow * ROWB + sh * 64;
    const uint32_t stsB = stsA + ATILE;

    uint32_t a_addr[2], b_addr[4];
    {
        const int ar = wm * 32 + (lane & 15);
        const int ac = lane >> 4;
        #pragma unroll
        for (int t = 0; t < 2; ++t)
            a_addr[t] = smbase + (uint32_t)(ar + t * 16) * ROWB + ac * 16;
        const int br = wn * 64 + (lane & 7) + ((lane >> 4) << 3);
        const int bc = (lane >> 3) & 1;
        #pragma unroll
        for (int u = 0; u < 4; ++u)
            b_addr[u] = smbase + ATILE + (uint32_t)(br + u * 16) * ROWB + bc * 16;
    }

    float c[2][8][4];
    #pragma unroll
    for (int t = 0; t < 2; ++t)
        #pragma unroll
        for (int j = 0; j < 8; ++j)
            #pragma unroll
            for (int r = 0; r < 4; ++r)
                c[t][j][r] = 0.0f;

    const int KT = K / TBK;

    // prologue: stage 0
    #pragma unroll
    for (int j = 0; j < 4; ++j) {
        cp16(stsA + j * 16, gA + j * 8);
        cp16(stsB + j * 16, gB + j * 8);
    }
    asm volatile("cp.async.commit_group;" ::: "memory");

    for (int kt = 0; kt < KT; ++kt) {
        asm volatile("cp.async.wait_group 0;" ::: "memory");
        __syncthreads();

        const int ns = kt + 1;
        if (ns < KT) {
            const uint32_t so = (uint32_t)(ns & 1) * STAGEB;
            const int kp = ns * TBK;
            #pragma unroll
            for (int j = 0; j < 4; ++j) {
                cp16(stsA + so + j * 16, gA + kp + j * 8);
                cp16(stsB + so + j * 16, gB + kp + j * 8);
            }
        }
        asm volatile("cp.async.commit_group;" ::: "memory");

        const uint32_t soff = (uint32_t)(kt & 1) * STAGEB;
        #pragma unroll
        for (int s = 0; s < 4; ++s) {
            uint32_t af[2][4], bf[4][4];
            #pragma unroll
            for (int t = 0; t < 2; ++t)
                ldsm4(a_addr[t] + soff + s * 32,
                      af[t][0], af[t][1], af[t][2], af[t][3]);
            #pragma unroll
            for (int u = 0; u < 4; ++u)
                ldsm4(b_addr[u] + soff + s * 32,
                      bf[u][0], bf[u][1], bf[u][2], bf[u][3]);
            #pragma unroll
            for (int t = 0; t < 2; ++t)
                #pragma unroll
                for (int j = 0; j < 8; ++j)
                    mma16816(c[t][j], af[t], &bf[j >> 1][(j & 1) * 2]);
        }
    }

    #pragma unroll
    for (int t = 0; t < 2; ++t) {
        const int m0 = bm + wm * 32 + t * 16 + (lane >> 2);
        #pragma unroll
        for (int j = 0; j < 8; ++j) {
            const int n0 = bn + wn * 64 + j * 8 + (lane & 3) * 2;
            float v0 = c[t][j][0] * alpha;
            float v1 = c[t][j][1] * alpha;
            float v2 = c[t][j][2] * alpha;
            float v3 = c[t][j][3] * alpha;
            if (outMode == 0) {
                float* C = (float*)Cv + bz * sCb + hz * sCh;
                if (bias) {
                    const float b0 = bias[n0], b1 = bias[n0 + 1];
                    v0 += b0; v1 += b1; v2 += b0; v3 += b1;
                }
                *(float2*)(C + (long long)m0 * ldc + n0) = make_float2(v0, v1);
                *(float2*)(C + (long long)(m0 + 8) * ldc + n0) = make_float2(v2, v3);
            } else {
                __half* C = (__half*)Cv + bz * sCb + hz * sCh;
                __half2 lo = __floats2half2_rn(v0, v1);
                __half2 hi = __floats2half2_rn(v2, v3);
                *(__half2*)(C + (long long)m0 * ldc + n0) = lo;
                *(__half2*)(C + (long long)(m0 + 8) * ldc + n0) = hi;
            }
        }
    }
}

// ---------------------------------------------------------------------------
// HMMA fp16 NN GEMM (PV): C[m,n] = sum_k A[m,k] * B[k,n], fp16 out.
// B natural [K, N] (ldb); B frags via ldmatrix.trans. TBK=64, double-buffered.
// ---------------------------------------------------------------------------
__global__ __launch_bounds__(NTHREADS, 2)
void gemm_hmma16_nn(const __half* __restrict__ A, const __half* __restrict__ B,
                    __half* __restrict__ C,
                    int K, int lda, int ldb, int ldc, int nh,
                    long long sAb, long long sAh, long long sBb, long long sBh,
                    long long sCb, long long sCh)
{
    extern __shared__ __align__(16) char sm[];
    const uint32_t smbase = smem_u32(sm);

    const int tid = threadIdx.x;
    const int lane = tid & 31, wid = tid >> 5;
    const int wm = wid & 3, wn = wid >> 2;

    const int z = blockIdx.z, bz = z / nh, hz = z - bz * nh;
    A += bz * sAb + hz * sAh;
    B += bz * sBb + hz * sBh;
    C += bz * sCb + hz * sCh;
    const int bm = blockIdx.y * TBM, bn = blockIdx.x * TBN;

    // A staging: 2 threads/row, 4 chunks each
    const int srow = tid >> 1;
    const int sh   = tid & 1;
    const __half* gA = A + (long long)(bm + srow) * lda + sh * 32;
    const uint32_t stsA = smbase + (uint32_t)srow * ROWB + sh * 64;

    // B staging: 64 k-rows x 16 chunks; 4 threads/row, 4 chunks each (stride 4)
    const int brow = tid >> 2;
    const int bch0 = tid & 3;
    const __half* gB = B + (long long)brow * ldb + bn + bch0 * 8;
    const uint32_t stsB = smbase + ATILE + (uint32_t)brow * BROWB + bch0 * 16;

    uint32_t a_addr[2], b_addr[4];
    {
        const int ar = wm * 32 + (lane & 15);
        const int ac = lane >> 4;
        #pragma unroll
        for (int t = 0; t < 2; ++t)
            a_addr[t] = smbase + (uint32_t)(ar + t * 16) * ROWB + ac * 16;
        #pragma unroll
        for (int u = 0; u < 4; ++u)
            b_addr[u] = smbase + ATILE + (uint32_t)(lane & 15) * BROWB
                        + (uint32_t)(wn * 64 + u * 16) * 2 + ((lane >> 4) << 4);
    }

    float c[2][8][4];
    #pragma unroll
    for (int t = 0; t < 2; ++t)
        #pragma unroll
        for (int j = 0; j < 8; ++j)
            #pragma unroll
            for (int r = 0; r < 4; ++r)
                c[t][j][r] = 0.0f;

    const int KT = K / TBK;

    // prologue: stage 0
    #pragma unroll
    for (int j = 0; j < 4; ++j) {
        cp16(stsA + j * 16, gA + j * 8);
        cp16(stsB + j * 64, gB + j * 32);          // chunk idx bch0 + j*4
    }
    asm volatile("cp.async.commit_group;" ::: "memory");

    for (int kt = 0; kt < KT; ++kt) {
        asm volatile("cp.async.wait_group 0;" ::: "memory");
        __syncthreads();

        const int ns = kt + 1;
        if (ns < KT) {
            const uint32_t so = (uint32_t)(ns & 1) * STAGEB_NN;
            const int kp = ns * TBK;
            #pragma unroll
            for (int j = 0; j < 4; ++j) {
                cp16(stsA + so + j * 16, gA + kp + j * 8);
                cp16(stsB + so + j * 64, gB + (long long)kp * ldb + j * 32);
            }
        }
        asm volatile("cp.async.commit_group;" ::: "memory");

        const uint32_t soff = (uint32_t)(kt & 1) * STAGEB_NN;
        #pragma unroll
        for (int s = 0; s < 4; ++s) {
            uint32_t af[2][4], bf[4][4];
            #pragma unroll
            for (int t = 0; t < 2; ++t)
                ldsm4(a_addr[t] + soff + s * 32,
                      af[t][0], af[t][1], af[t][2], af[t][3]);
            #pragma unroll
            for (int u = 0; u < 4; ++u)
                ldsm4t(b_addr[u] + soff + (uint32_t)s * 16 * BROWB,
                       bf[u][0], bf[u][1], bf[u][2], bf[u][3]);
            #pragma unroll
            for (int t = 0; t < 2; ++t)
                #pragma unroll
                for (int u = 0; u < 4; ++u) {
                    mma16816(c[t][2 * u],     af[t], &bf[u][0]);
                    mma16816(c[t][2 * u + 1], af[t], &bf[u][2]);
                }
        }
    }

    #pragma unroll
    for (int t = 0; t < 2; ++t) {
        const int m0 = bm + wm * 32 + t * 16 + (lane >> 2);
        #pragma unroll
        for (int j = 0; j < 8; ++j) {
            const int n0 = bn + wn * 64 + j * 8 + (lane & 3) * 2;
            __half2 lo = __floats2half2_rn(c[t][j][0], c[t][j][1]);
            __half2 hi = __floats2half2_rn(c[t][j][2], c[t][j][3]);
            *(__half2*)(C + (long long)m0 * ldc + n0) = lo;
            *(__half2*)(C + (long long)(m0 + 8) * ldc + n0) = hi;
        }
    }
}

// ---------------------------------------------------------------------------
// Row softmax in base-2: fp16 scores -> fp16 probs. 2048 cols, 256 threads.
// ---------------------------------------------------------------------------
__device__ __forceinline__ float warp_max(float v) {
    #pragma unroll
    for (int o = 16; o > 0; o >>= 1) v = fmaxf(v, __shfl_xor_sync(0xffffffffu, v, o));
    return v;
}
__device__ __forceinline__ float warp_sum(float v) {
    #pragma unroll
    for (int o = 16; o > 0; o >>= 1) v += __shfl_xor_sync(0xffffffffu, v, o);
    return v;
}

__global__ __launch_bounds__(256)
void softmax16_kernel(const __half* __restrict__ S, __half* __restrict__ P)
{
    const long long rowoff = (long long)blockIdx.x * SEQ;
    const int tid = threadIdx.x;
    const int wid = tid >> 5, lid = tid & 31;
    __shared__ float red[8];

    uint4 raw = *(const uint4*)(S + rowoff + tid * 8);
    const __half2* hp = (const __half2*)&raw;
    float v[8];
    #pragma unroll
    for (int i = 0; i < 4; ++i) {
        float2 f = __half22float2(hp[i]);
        v[2 * i] = f.x;
        v[2 * i + 1] = f.y;
    }

    float m = -1e30f;
    #pragma unroll
    for (int i = 0; i < 8; ++i) m = fmaxf(m, v[i]);
    m = warp_max(m);
    if (lid == 0) red[wid] = m;
    __syncthreads();
    if (wid == 0) {
        float t = (lid < 8) ? red[lid] : -1e30f;
        t = warp_max(t);
        if (lid == 0) red[0] = t;
    }
    __syncthreads();
    m = red[0];
    __syncthreads();

    float s = 0.0f;
    #pragma unroll
    for (int i = 0; i < 8; ++i) {
        v[i] = exp2a(v[i] - m);
        s += v[i];
    }
    s = warp_sum(s);
    if (lid == 0) red[wid] = s;
    __syncthreads();
    if (wid == 0) {
        float t = (lid < 8) ? red[lid] : 0.0f;
        t = warp_sum(t);
        if (lid == 0) red[0] = t;
    }
    __syncthreads();
    const float inv = 1.0f / red[0];

    __half2 h[4];
    #pragma unroll
    for (int i = 0; i < 4; ++i)
        h[i] = __floats2half2_rn(v[2 * i] * inv, v[2 * i + 1] * inv);
    *(uint4*)(P + rowoff + tid * 8) = *(uint4*)h;
}

// ---------------------------------------------------------------------------
extern "C" void kernel_launch(void* const* d_in, const int* in_sizes, int n_in,
                              void* d_out, int out_size)
{
    const float* q  = (const float*)d_in[0];
    const float* kv = (const float*)d_in[1];
    const float* Wq = (const float*)d_in[2];
    const float* Wk = (const float*)d_in[3];
    const float* Wv = (const float*)d_in[4];
    const float* Wo = (const float*)d_in[5];
    const float* bo = (const float*)d_in[6];
    float* out = (float*)d_out;

    __half *q16, *kv16, *wq16, *wkv16, *wo16;
    __half *qp16, *kvp16, *ctx16, *sc16, *p16;
    cudaGetSymbolAddress((void**)&q16,   g_q16);
    cudaGetSymbolAddress((void**)&kv16,  g_kv16);
    cudaGetSymbolAddress((void**)&wq16,  g_wq16);
    cudaGetSymbolAddress((void**)&wkv16, g_wkv16);
    cudaGetSymbolAddress((void**)&wo16,  g_wo16);
    cudaGetSymbolAddress((void**)&qp16,  g_qp16);
    cudaGetSymbolAddress((void**)&kvp16, g_kvp16);
    cudaGetSymbolAddress((void**)&ctx16, g_ctx16);
    cudaGetSymbolAddress((void**)&sc16,  g_sc16);
    cudaGetSymbolAddress((void**)&p16,   g_p16);

    cudaFuncSetAttribute(gemm_hmma16, cudaFuncAttributeMaxDynamicSharedMemorySize,
                         SMEM_TOTAL);
    cudaFuncSetAttribute(gemm_hmma16_nn, cudaFuncAttributeMaxDynamicSharedMemorySize,
                         SMEM_NN);

    const int MT = BATCH * SEQ;        // 8192
    const int DKV2 = 2 * DQ;           // 2048 (combined kp|vp width)

    // 0) all fp32 -> fp16 conversions in ONE launch; Wk/Wv into one buffer
    {
        ConvArgs a;
        a.seg[0] = { (const float4*)q,  (uint2*)q16,  (long long)BATCH * SEQ * DQ  / 4, 1.0f };
        a.seg[1] = { (const float4*)kv, (uint2*)kv16, (long long)BATCH * SEQ * DKV / 4, 1.0f };
        a.seg[2] = { (const float4*)Wq, (uint2*)wq16, (long long)DQ * DQ  / 4, QK_SCALE };
        a.seg[3] = { (const float4*)Wk, (uint2*)wkv16, (long long)DQ * DKV / 4, 1.0f };
        a.seg[4] = { (const float4*)Wv, (uint2*)(wkv16 + (long long)DQ * DKV),
                     (long long)DQ * DKV / 4, 1.0f };
        a.seg[5] = { (const float4*)Wo, (uint2*)wo16, (long long)DQ * DQ  / 4, 1.0f };
        long long total = 0;
        for (int i = 0; i < 6; ++i) total += a.seg[i].n;
        conv6_kernel<<<(int)((total + 255) / 256), 256>>>(a, total);
    }

    // 1) qp16 = q16 @ (Wq*scale)^T          (launch 1)
    gemm_hmma16<<<dim3(DQ / TBN, MT / TBM, 1), NTHREADS, SMEM_TOTAL>>>(
        q16, wq16, nullptr, qp16, DQ, DQ, DQ, DQ, 1,
        0, 0, 0, 0, 0, 0, 1.0f, 1);

    // 2) kvp16 = kv16 @ [Wk;Wv]^T  (N=2048: cols 0-1023 kp, 1024-2047 vp)
    gemm_hmma16<<<dim3(DKV2 / TBN, MT / TBM, 1), NTHREADS, SMEM_TOTAL>>>(
        kv16, wkv16, nullptr, kvp16, DKV, DKV, DKV, DKV2, 1,
        0, 0, 0, 0, 0, 0, 1.0f, 1);

    // 3) sc16[b,h] = qh @ kh^T (log2-domain) (launch 3)
    gemm_hmma16<<<dim3(SEQ / TBN, SEQ / TBM, BATCH * NH), NTHREADS, SMEM_TOTAL>>>(
        qp16, kvp16, nullptr, sc16, HD, DQ, DKV2, SEQ, NH,
        (long long)SEQ * DQ, HD,
        (long long)SEQ * DKV2, HD,
        (long long)NH * SEQ * SEQ, (long long)SEQ * SEQ,
        1.0f, 1);

    // 4) softmax (base-2)                   (launch 4)
    softmax16_kernel<<<dim3(BATCH * NH * SEQ), dim3(256)>>>(sc16, p16);

    // 5) ctx16 = P @ vp (NN; vp = kvp16 cols 1024+) (launch 5 -> ncu target)
    gemm_hmma16_nn<<<dim3(HD / TBN, SEQ / TBM, BATCH * NH), NTHREADS, SMEM_NN>>>(
        p16, kvp16 + DQ, ctx16, SEQ, SEQ, DKV2, DQ, NH,
        (long long)NH * SEQ * SEQ, (long long)SEQ * SEQ,
        (long long)SEQ * DKV2, HD,
        (long long)SEQ * DQ, HD);

    // 6) out = ctx16 @ Wo^T + bo  (fp32 out) (launch 6)
    gemm_hmma16<<<dim3(DQ / TBN, MT / TBM, 1), NTHREADS, SMEM_TOTAL>>>(
        ctx16, wo16, bo, out, DQ, DQ, DQ, DQ, 1,
        0, 0, 0, 0, 0, 0, 1.0f, 0);
}

// round 17
// speedup vs baseline: 1.9262x; 1.9262x over previous
#include <cuda_runtime.h>
#include <cuda_fp16.h>
#include <cstdint>
#include <math.h>

// Problem constants
#define BATCH 4
#define SEQ   2048
#define DQ    1024
#define DKV   768
#define NH    4
#define HD    256

// HMMA GEMM tiling (round-13 proven config)
#define TBM 128
#define TBN 128
#define TBK 32
#define NTHREADS 256
#define ROWB  80
#define ATILE (128 * ROWB)             // 10240
#define STAGEB (2 * ATILE)             // 20480
#define NSTAGE 4
#define SMEM_TOTAL (NSTAGE * STAGEB)   // 81920 B

// NN-mode B tile: 32 k-rows x 128 n-cols fp16, 16B row pad
#define BROWB 272
#define BTILE (32 * BROWB)             // 8704
#define STAGEB_NN (ATILE + BTILE)      // 18944
#define SMEM_NN (NSTAGE * STAGEB_NN)   // 75776 B

#define QK_SCALE 0.09016844005555897f  // log2(e) / 16

// -------- scratch (device globals; no cudaMalloc allowed) -------------------
__device__ __half g_q16 [(long long)BATCH * SEQ * DQ];
__device__ __half g_kv16[(long long)BATCH * SEQ * DKV];
__device__ __half g_wq16[DQ * DQ];
__device__ __half g_wk16[DQ * DKV];
__device__ __half g_wv16[DQ * DKV];
__device__ __half g_wo16[DQ * DQ];
__device__ __half g_qp16 [(long long)BATCH * SEQ * DQ];
__device__ __half g_kp16 [(long long)BATCH * SEQ * DQ];
__device__ __half g_vp16 [(long long)BATCH * SEQ * DQ];
__device__ __half g_ctx16[(long long)BATCH * SEQ * DQ];
__device__ __half g_sc16 [(long long)BATCH * NH * SEQ * SEQ]; // fp16 scores
__device__ __half g_p16  [(long long)BATCH * NH * SEQ * SEQ]; // fp16 probs

// ---------------------------- helpers ---------------------------------------
__device__ __forceinline__ uint32_t smem_u32(const void* p) {
    uint32_t a;
    asm("{ .reg .u64 t; cvta.to.shared.u64 t, %1; cvt.u32.u64 %0, t; }"
        : "=r"(a) : "l"(p));
    return a;
}

__device__ __forceinline__ void cp16(uint32_t dst, const void* src) {
    asm volatile("cp.async.cg.shared.global [%0], [%1], 16;"
                 :: "r"(dst), "l"(src) : "memory");
}

__device__ __forceinline__ void ldsm4(uint32_t addr, uint32_t& r0, uint32_t& r1,
                                      uint32_t& r2, uint32_t& r3) {
    asm volatile("ldmatrix.sync.aligned.m8n8.x4.shared.b16 {%0,%1,%2,%3}, [%4];"
                 : "=r"(r0), "=r"(r1), "=r"(r2), "=r"(r3) : "r"(addr));
}

__device__ __forceinline__ void ldsm4t(uint32_t addr, uint32_t& r0, uint32_t& r1,
                                       uint32_t& r2, uint32_t& r3) {
    asm volatile("ldmatrix.sync.aligned.m8n8.x4.trans.shared.b16 {%0,%1,%2,%3}, [%4];"
                 : "=r"(r0), "=r"(r1), "=r"(r2), "=r"(r3) : "r"(addr));
}

__device__ __forceinline__ void mma16816(float* c, const uint32_t* a,
                                         const uint32_t* b) {
    asm volatile(
        "mma.sync.aligned.m16n8k16.row.col.f32.f16.f16.f32 "
        "{%0,%1,%2,%3}, {%4,%5,%6,%7}, {%8,%9}, {%0,%1,%2,%3};"
        : "+f"(c[0]), "+f"(c[1]), "+f"(c[2]), "+f"(c[3])
        : "r"(a[0]), "r"(a[1]), "r"(a[2]), "r"(a[3]), "r"(b[0]), "r"(b[1]));
}

__device__ __forceinline__ float exp2a(float x) {
    float r;
    asm("ex2.approx.f32 %0, %1;" : "=f"(r) : "f"(x));
    return r;
}

// ---------------------------------------------------------------------------
// Segmented fp32 -> fp16 conversion, by-value args, 4 elements/thread (MLP=4)
// ---------------------------------------------------------------------------
struct ConvSeg { const float4* s; uint2* d; long long n; float m; };
struct ConvArgs { ConvSeg seg[6]; };

__device__ __forceinline__ void conv_one(const ConvArgs& a, long long i) {
    #pragma unroll
    for (int k = 0; k < 6; ++k) {
        if (i < a.seg[k].n) {
            float4 v = a.seg[k].s[i];
            const float m = a.seg[k].m;
            __half2 h0 = __floats2half2_rn(v.x * m, v.y * m);
            __half2 h1 = __floats2half2_rn(v.z * m, v.w * m);
            uint2 u;
            u.x = *reinterpret_cast<uint32_t*>(&h0);
            u.y = *reinterpret_cast<uint32_t*>(&h1);
            a.seg[k].d[i] = u;
            return;
        }
        i -= a.seg[k].n;
    }
}

__global__ void conv6_kernel(ConvArgs a, long long total)
{
    const long long i0 = (long long)blockIdx.x * (blockDim.x * 4) + threadIdx.x;
    #pragma unroll
    for (int r = 0; r < 4; ++r) {
        const long long i = i0 + (long long)r * 256;
        if (i < total) conv_one(a, i);
    }
}

// ---------------------------------------------------------------------------
// HMMA fp16 NT GEMM, cp.async 4-stage, 2 CTAs/SM (round-13 kernel).
//   C[m,n] = alpha * sum_k A[m,k]*B[n,k]  (+ bias[n] if mode 0)
// outMode: 0 = fp32 C (+bias), 1 = fp16 C
// ---------------------------------------------------------------------------
__global__ __launch_bounds__(NTHREADS, 2)
void gemm_hmma16(const __half* __restrict__ A, const __half* __restrict__ B,
                 const float* __restrict__ bias, void* __restrict__ Cv,
                 int K, int lda, int ldb, int ldc, int nh,
                 long long sAb, long long sAh, long long sBb, long long sBh,
                 long long sCb, long long sCh, float alpha, int outMode)
{
    extern __shared__ __align__(16) char sm[];
    const uint32_t smbase = smem_u32(sm);

    const int tid = threadIdx.x;
    const int lane = tid & 31, wid = tid >> 5;
    const int wm = wid & 3, wn = wid >> 2;

    const int z = blockIdx.z, bz = z / nh, hz = z - bz * nh;
    A += bz * sAb + hz * sAh;
    B += bz * sBb + hz * sBh;
    const int bm = blockIdx.y * TBM, bn = blockIdx.x * TBN;

    const int srow = tid >> 2;
    const int sc   = tid & 3;
    const __half* gA = A + (long long)(bm + srow) * lda + sc * 8;
    const __half* gB = B + (long long)(bn + srow) * ldb + sc * 8;
    const uint32_t stsA = smbase + (uint32_t)srow * ROWB + sc * 16;
    const uint32_t stsB = stsA + ATILE;
    const long long a64 = 64LL * lda, b64 = 64LL * ldb;

    uint32_t a_addr[2], b_addr[4];
    {
        const int ar = wm * 32 + (lane & 15);
        const int ac = lane >> 4;
        #pragma unroll
        for (int t = 0; t < 2; ++t)
            a_addr[t] = smbase + (uint32_t)(ar + t * 16) * ROWB + ac * 16;
        const int br = wn * 64 + (lane & 7) + ((lane >> 4) << 3);
        const int bc = (lane >> 3) & 1;
        #pragma unroll
        for (int u = 0; u < 4; ++u)
            b_addr[u] = smbase + ATILE + (uint32_t)(br + u * 16) * ROWB + bc * 16;
    }

    float c[2][8][4];
    #pragma unroll
    for (int t = 0; t < 2; ++t)
        #pragma unroll
        for (int j = 0; j < 8; ++j)
            #pragma unroll
            for (int r = 0; r < 4; ++r)
                c[t][j][r] = 0.0f;

    const int KT = K / TBK;

    #pragma unroll
    for (int p = 0; p < NSTAGE - 1; ++p) {
        const uint32_t so = (uint32_t)p * STAGEB;
        const int kp = p * TBK;
        cp16(stsA + so, gA + kp);
        cp16(stsA + so + 64 * ROWB, gA + kp + a64);
        cp16(stsB + so, gB + kp);
        cp16(stsB + so + 64 * ROWB, gB + kp + b64);
        asm volatile("cp.async.commit_group;" ::: "memory");
    }

    for (int kt = 0; kt < KT; ++kt) {
        asm volatile("cp.async.wait_group %0;" :: "n"(NSTAGE - 2) : "memory");
        __syncthreads();

        const int ns = kt + NSTAGE - 1;
        if (ns < KT) {
            const uint32_t so = (uint32_t)(ns & (NSTAGE - 1)) * STAGEB;
            const int kp = ns * TBK;
            cp16(stsA + so, gA + kp);
            cp16(stsA + so + 64 * ROWB, gA + kp + a64);
            cp16(stsB + so, gB + kp);
            cp16(stsB + so + 64 * ROWB, gB + kp + b64);
        }
        asm volatile("cp.async.commit_group;" ::: "memory");

        const uint32_t soff = (uint32_t)(kt & (NSTAGE - 1)) * STAGEB;
        #pragma unroll
        for (int s = 0; s < 2; ++s) {
            uint32_t af[2][4], bf[4][4];
            #pragma unroll
            for (int t = 0; t < 2; ++t)
                ldsm4(a_addr[t] + soff + s * 32,
                      af[t][0], af[t][1], af[t][2], af[t][3]);
            #pragma unroll
            for (int u = 0; u < 4; ++u)
                ldsm4(b_addr[u] + soff + s * 32,
                      bf[u][0], bf[u][1], bf[u][2], bf[u][3]);
            #pragma unroll
            for (int t = 0; t < 2; ++t)
                #pragma unroll
                for (int j = 0; j < 8; ++j)
                    mma16816(c[t][j], af[t], &bf[j >> 1][(j & 1) * 2]);
        }
    }

    #pragma unroll
    for (int t = 0; t < 2; ++t) {
        const int m0 = bm + wm * 32 + t * 16 + (lane >> 2);
        #pragma unroll
        for (int j = 0; j < 8; ++j) {
            const int n0 = bn + wn * 64 + j * 8 + (lane & 3) * 2;
            float v0 = c[t][j][0] * alpha;
            float v1 = c[t][j][1] * alpha;
            float v2 = c[t][j][2] * alpha;
            float v3 = c[t][j][3] * alpha;
            if (outMode == 0) {
                float* C = (float*)Cv + bz * sCb + hz * sCh;
                if (bias) {
                    const float b0 = bias[n0], b1 = bias[n0 + 1];
                    v0 += b0; v1 += b1; v2 += b0; v3 += b1;
                }
                *(float2*)(C + (long long)m0 * ldc + n0) = make_float2(v0, v1);
                *(float2*)(C + (long long)(m0 + 8) * ldc + n0) = make_float2(v2, v3);
            } else {
                __half* C = (__half*)Cv + bz * sCb + hz * sCh;
                __half2 lo = __floats2half2_rn(v0, v1);
                __half2 hi = __floats2half2_rn(v2, v3);
                *(__half2*)(C + (long long)m0 * ldc + n0) = lo;
                *(__half2*)(C + (long long)(m0 + 8) * ldc + n0) = hi;
            }
        }
    }
}

// ---------------------------------------------------------------------------
// HMMA fp16 NN GEMM (PV): C[m,n] = sum_k A[m,k] * B[k,n], fp16 out.
// B natural [K, N]; B frags via ldmatrix.trans. (round-13 kernel)
// ---------------------------------------------------------------------------
__global__ __launch_bounds__(NTHREADS, 2)
void gemm_hmma16_nn(const __half* __restrict__ A, const __half* __restrict__ B,
                    __half* __restrict__ C,
                    int K, int lda, int ldb, int ldc, int nh,
                    long long sAb, long long sAh, long long sBb, long long sBh,
                    long long sCb, long long sCh)
{
    extern __shared__ __align__(16) char sm[];
    const uint32_t smbase = smem_u32(sm);

    const int tid = threadIdx.x;
    const int lane = tid & 31, wid = tid >> 5;
    const int wm = wid & 3, wn = wid >> 2;

    const int z = blockIdx.z, bz = z / nh, hz = z - bz * nh;
    A += bz * sAb + hz * sAh;
    B += bz * sBb + hz * sBh;
    C += bz * sCb + hz * sCh;
    const int bm = blockIdx.y * TBM, bn = blockIdx.x * TBN;

    const int srow = tid >> 2;
    const int sc   = tid & 3;
    const __half* gA = A + (long long)(bm + srow) * lda + sc * 8;
    const uint32_t stsA = smbase + (uint32_t)srow * ROWB + sc * 16;
    const long long a64 = 64LL * lda;

    const int br0 = tid >> 4, bc0 = tid & 15;
    const int br1 = (tid + 256) >> 4, bc1 = tid & 15;
    const __half* gB0 = B + (long long)br0 * ldb + bn + bc0 * 8;
    const __half* gB1 = B + (long long)br1 * ldb + bn + bc1 * 8;
    const uint32_t stsB0 = smbase + ATILE + (uint32_t)br0 * BROWB + bc0 * 16;
    const uint32_t stsB1 = smbase + ATILE + (uint32_t)br1 * BROWB + bc1 * 16;

    uint32_t a_addr[2], b_addr[4];
    {
        const int ar = wm * 32 + (lane & 15);
        const int ac = lane >> 4;
        #pragma unroll
        for (int t = 0; t < 2; ++t)
            a_addr[t] = smbase + (uint32_t)(ar + t * 16) * ROWB + ac * 16;
        #pragma unroll
        for (int u = 0; u < 4; ++u)
            b_addr[u] = smbase + ATILE + (uint32_t)(lane & 15) * BROWB
                        + (uint32_t)(wn * 64 + u * 16) * 2 + ((lane >> 4) << 4);
    }

    float c[2][8][4];
    #pragma unroll
    for (int t = 0; t < 2; ++t)
        #pragma unroll
        for (int j = 0; j < 8; ++j)
            #pragma unroll
            for (int r = 0; r < 4; ++r)
                c[t][j][r] = 0.0f;

    const int KT = K / TBK;

    #pragma unroll
    for (int p = 0; p < NSTAGE - 1; ++p) {
        const uint32_t so = (uint32_t)p * STAGEB_NN;
        const int kp = p * TBK;
        cp16(stsA + so, gA + kp);
        cp16(stsA + so + 64 * ROWB, gA + kp + a64);
        cp16(stsB0 + so, gB0 + (long long)kp * ldb);
        cp16(stsB1 + so, gB1 + (long long)kp * ldb);
        asm volatile("cp.async.commit_group;" ::: "memory");
    }

    for (int kt = 0; kt < KT; ++kt) {
        asm volatile("cp.async.wait_group %0;" :: "n"(NSTAGE - 2) : "memory");
        __syncthreads();

        const int ns = kt + NSTAGE - 1;
        if (ns < KT) {
            const uint32_t so = (uint32_t)(ns & (NSTAGE - 1)) * STAGEB_NN;
            const int kp = ns * TBK;
            cp16(stsA + so, gA + kp);
            cp16(stsA + so + 64 * ROWB, gA + kp + a64);
            cp16(stsB0 + so, gB0 + (long long)kp * ldb);
            cp16(stsB1 + so, gB1 + (long long)kp * ldb);
        }
        asm volatile("cp.async.commit_group;" ::: "memory");

        const uint32_t soff = (uint32_t)(kt & (NSTAGE - 1)) * STAGEB_NN;
        #pragma unroll
        for (int s = 0; s < 2; ++s) {
            uint32_t af[2][4], bf[4][4];
            #pragma unroll
            for (int t = 0; t < 2; ++t)
                ldsm4(a_addr[t] + soff + s * 32,
                      af[t][0], af[t][1], af[t][2], af[t][3]);
            #pragma unroll
            for (int u = 0; u < 4; ++u)
                ldsm4t(b_addr[u] + soff + (uint32_t)s * 16 * BROWB,
                       bf[u][0], bf[u][1], bf[u][2], bf[u][3]);
            #pragma unroll
            for (int t = 0; t < 2; ++t)
                #pragma unroll
                for (int u = 0; u < 4; ++u) {
                    mma16816(c[t][2 * u],     af[t], &bf[u][0]);
                    mma16816(c[t][2 * u + 1], af[t], &bf[u][2]);
                }
        }
    }

    #pragma unroll
    for (int t = 0; t < 2; ++t) {
        const int m0 = bm + wm * 32 + t * 16 + (lane >> 2);
        #pragma unroll
        for (int j = 0; j < 8; ++j) {
            const int n0 = bn + wn * 64 + j * 8 + (lane & 3) * 2;
            __half2 lo = __floats2half2_rn(c[t][j][0], c[t][j][1]);
            __half2 hi = __floats2half2_rn(c[t][j][2], c[t][j][3]);
            *(__half2*)(C + (long long)m0 * ldc + n0) = lo;
            *(__half2*)(C + (long long)(m0 + 8) * ldc + n0) = hi;
        }
    }
}

// ---------------------------------------------------------------------------
// Row softmax in base-2: fp16 scores -> fp16 probs. 2048 cols, 256 threads.
// ---------------------------------------------------------------------------
__device__ __forceinline__ float warp_max(float v) {
    #pragma unroll
    for (int o = 16; o > 0; o >>= 1) v = fmaxf(v, __shfl_xor_sync(0xffffffffu, v, o));
    return v;
}
__device__ __forceinline__ float warp_sum(float v) {
    #pragma unroll
    for (int o = 16; o > 0; o >>= 1) v += __shfl_xor_sync(0xffffffffu, v, o);
    return v;
}

__global__ __launch_bounds__(256)
void softmax16_kernel(const __half* __restrict__ S, __half* __restrict__ P)
{
    const long long rowoff = (long long)blockIdx.x * SEQ;
    const int tid = threadIdx.x;
    const int wid = tid >> 5, lid = tid & 31;
    __shared__ float red[8];

    uint4 raw = *(const uint4*)(S + rowoff + tid * 8);
    const __half2* hp = (const __half2*)&raw;
    float v[8];
    #pragma unroll
    for (int i = 0; i < 4; ++i) {
        float2 f = __half22float2(hp[i]);
        v[2 * i] = f.x;
        v[2 * i + 1] = f.y;
    }

    float m = -1e30f;
    #pragma unroll
    for (int i = 0; i < 8; ++i) m = fmaxf(m, v[i]);
    m = warp_max(m);
    if (lid == 0) red[wid] = m;
    __syncthreads();
    if (wid == 0) {
        float t = (lid < 8) ? red[lid] : -1e30f;
        t = warp_max(t);
        if (lid == 0) red[0] = t;
    }
    __syncthreads();
    m = red[0];
    __syncthreads();

    float s = 0.0f;
    #pragma unroll
    for (int i = 0; i < 8; ++i) {
        v[i] = exp2a(v[i] - m);
        s += v[i];
    }
    s = warp_sum(s);
    if (lid == 0) red[wid] = s;
    __syncthreads();
    if (wid == 0) {
        float t = (lid < 8) ? red[lid] : 0.0f;
        t = warp_sum(t);
        if (lid == 0) red[0] = t;
    }
    __syncthreads();
    const float inv = 1.0f / red[0];

    __half2 h[4];
    #pragma unroll
    for (int i = 0; i < 4; ++i)
        h[i] = __floats2half2_rn(v[2 * i] * inv, v[2 * i + 1] * inv);
    *(uint4*)(P + rowoff + tid * 8) = *(uint4*)h;
}

// ---------------------------------------------------------------------------
extern "C" void kernel_launch(void* const* d_in, const int* in_sizes, int n_in,
                              void* d_out, int out_size)
{
    const float* q  = (const float*)d_in[0];
    const float* kv = (const float*)d_in[1];
    const float* Wq = (const float*)d_in[2];
    const float* Wk = (const float*)d_in[3];
    const float* Wv = (const float*)d_in[4];
    const float* Wo = (const float*)d_in[5];
    const float* bo = (const float*)d_in[6];
    float* out = (float*)d_out;

    __half *q16, *kv16, *wq16, *wk16, *wv16, *wo16;
    __half *qp16, *kp16, *vp16, *ctx16, *sc16, *p16;
    cudaGetSymbolAddress((void**)&q16,  g_q16);
    cudaGetSymbolAddress((void**)&kv16, g_kv16);
    cudaGetSymbolAddress((void**)&wq16, g_wq16);
    cudaGetSymbolAddress((void**)&wk16, g_wk16);
    cudaGetSymbolAddress((void**)&wv16, g_wv16);
    cudaGetSymbolAddress((void**)&wo16, g_wo16);
    cudaGetSymbolAddress((void**)&qp16,  g_qp16);
    cudaGetSymbolAddress((void**)&kp16,  g_kp16);
    cudaGetSymbolAddress((void**)&vp16,  g_vp16);
    cudaGetSymbolAddress((void**)&ctx16, g_ctx16);
    cudaGetSymbolAddress((void**)&sc16,  g_sc16);
    cudaGetSymbolAddress((void**)&p16,   g_p16);

    cudaFuncSetAttribute(gemm_hmma16, cudaFuncAttributeMaxDynamicSharedMemorySize,
                         SMEM_TOTAL);
    cudaFuncSetAttribute(gemm_hmma16_nn, cudaFuncAttributeMaxDynamicSharedMemorySize,
                         SMEM_NN);

    const int MT = BATCH * SEQ;        // 8192

    // 0) all fp32 -> fp16 conversions in ONE launch, 4 elems/thread (launch 0)
    {
        ConvArgs a;
        a.seg[0] = { (const float4*)q,  (uint2*)q16,  (long long)BATCH * SEQ * DQ  / 4, 1.0f };
        a.seg[1] = { (const float4*)kv, (uint2*)kv16, (long long)BATCH * SEQ * DKV / 4, 1.0f };
        a.seg[2] = { (const float4*)Wq, (uint2*)wq16, (long long)DQ * DQ  / 4, QK_SCALE };
        a.seg[3] = { (const float4*)Wk, (uint2*)wk16, (long long)DQ * DKV / 4, 1.0f };
        a.seg[4] = { (const float4*)Wv, (uint2*)wv16, (long long)DQ * DKV / 4, 1.0f };
        a.seg[5] = { (const float4*)Wo, (uint2*)wo16, (long long)DQ * DQ  / 4, 1.0f };
        long long total = 0;
        for (int i = 0; i < 6; ++i) total += a.seg[i].n;
        conv6_kernel<<<(int)((total + 1023) / 1024), 256>>>(a, total);
    }

    // 1) qp16 = q16 @ (Wq*scale)^T          (launch 1)
    gemm_hmma16<<<dim3(DQ / TBN, MT / TBM, 1), NTHREADS, SMEM_TOTAL>>>(
        q16, wq16, nullptr, qp16, DQ, DQ, DQ, DQ, 1,
        0, 0, 0, 0, 0, 0, 1.0f, 1);

    // 2) kp16 = kv16 @ Wk^T                 (launch 2)
    gemm_hmma16<<<dim3(DQ / TBN, MT / TBM, 1), NTHREADS, SMEM_TOTAL>>>(
        kv16, wk16, nullptr, kp16, DKV, DKV, DKV, DQ, 1,
        0, 0, 0, 0, 0, 0, 1.0f, 1);

    // 3) vp16 = kv16 @ Wv^T (normal layout) (launch 3)
    gemm_hmma16<<<dim3(DQ / TBN, MT / TBM, 1), NTHREADS, SMEM_TOTAL>>>(
        kv16, wv16, nullptr, vp16, DKV, DKV, DKV, DQ, 1,
        0, 0, 0, 0, 0, 0, 1.0f, 1);

    // 4) sc16[b,h] = qh @ kh^T (log2-domain) (launch 4)
    gemm_hmma16<<<dim3(SEQ / TBN, SEQ / TBM, BATCH * NH), NTHREADS, SMEM_TOTAL>>>(
        qp16, kp16, nullptr, sc16, HD, DQ, DQ, SEQ, NH,
        (long long)SEQ * DQ, HD,
        (long long)SEQ * DQ, HD,
        (long long)NH * SEQ * SEQ, (long long)SEQ * SEQ,
        1.0f, 1);

    // 5) softmax (base-2)                   (launch 5)
    softmax16_kernel<<<dim3(BATCH * NH * SEQ), dim3(256)>>>(sc16, p16);

    // 6) ctx16 = P @ vp16 (NN)              (launch 6)
    gemm_hmma16_nn<<<dim3(HD / TBN, SEQ / TBM, BATCH * NH), NTHREADS, SMEM_NN>>>(
        p16, vp16, ctx16, SEQ, SEQ, DQ, DQ, NH,
        (long long)NH * SEQ * SEQ, (long long)SEQ * SEQ,
        (long long)SEQ * DQ, HD,
        (long long)SEQ * DQ, HD);

    // 7) out = ctx16 @ Wo^T + bo  (fp32 out) (launch 7)
    gemm_hmma16<<<dim3(DQ / TBN, MT / TBM, 1), NTHREADS, SMEM_TOTAL>>>(
        ctx16, wo16, bo, out, DQ, DQ, DQ, DQ, 1,
        0, 0, 0, 0, 0, 0, 1.0f, 0);
}